// round 3
// baseline (speedup 1.0000x reference)
#include <cuda_runtime.h>
#include <cuda_bf16.h>

// RandomPrompter: out[b,c,h,w] = x[b,c,h,w] + (patch inside per-sample 30x30 window)
// Shapes: x [256,3,224,224] f32, patch [1,3,30,30] f32, offsets [256,2] i32.
//
// Pure streaming (308 MB). Four float4s per thread (front-batched LDGs, MLP=4),
// streaming cache hints (ldcs/stcs) since there is zero reuse.

#define BATCH 256
#define CH    3
#define HH    224
#define WW    224
#define PSZ   30

#define W4        (WW / 4)                        // 56 float4 per row
#define TOTAL_V4  (BATCH * CH * HH * W4)          // 9,633,792 float4s
#define VPT       4                               // float4s per thread
#define TPB       256
#define TILE      (TPB * VPT)                     // 1024 float4s per block

__device__ __forceinline__ void patch_add(float4& val, int v,
                                          const float* __restrict__ patch,
                                          const int2* __restrict__ offsets)
{
    // v = ((b*3 + c)*224 + h)*56 + w4
    int w4 = v % W4;
    int t  = v / W4;
    int h  = t % HH;
    int t2 = t / HH;
    int c  = t2 % CH;
    int b  = t2 / CH;

    int2 off = __ldg(&offsets[b]);   // (row, col), each in [0, 194)
    int dh = h - off.x;
    if ((unsigned)dh < (unsigned)PSZ) {
        const float* prow = patch + (c * PSZ + dh) * PSZ;
        int dw = w4 * 4 - off.y;
        if ((unsigned)(dw + 0) < (unsigned)PSZ) val.x += __ldg(&prow[dw + 0]);
        if ((unsigned)(dw + 1) < (unsigned)PSZ) val.y += __ldg(&prow[dw + 1]);
        if ((unsigned)(dw + 2) < (unsigned)PSZ) val.z += __ldg(&prow[dw + 2]);
        if ((unsigned)(dw + 3) < (unsigned)PSZ) val.w += __ldg(&prow[dw + 3]);
    }
}

__global__ __launch_bounds__(TPB) void random_prompter_kernel(
    const float4* __restrict__ x,
    const float* __restrict__ patch,
    const int2* __restrict__ offsets,
    float4* __restrict__ out)
{
    int base = blockIdx.x * TILE + threadIdx.x;
    int v0 = base;
    int v1 = base + TPB;
    int v2 = base + 2 * TPB;
    int v3 = base + 3 * TPB;

    // TOTAL_V4 (9,633,792) is divisible by TILE (1024): 9408 blocks, no tail.
    // Front-batch all 4 LDGs before any consumer (MLP=4 per thread).
    float4 a = __ldcs(&x[v0]);
    float4 b = __ldcs(&x[v1]);
    float4 c = __ldcs(&x[v2]);
    float4 d = __ldcs(&x[v3]);

    patch_add(a, v0, patch, offsets);
    patch_add(b, v1, patch, offsets);
    patch_add(c, v2, patch, offsets);
    patch_add(d, v3, patch, offsets);

    __stcs(&out[v0], a);
    __stcs(&out[v1], b);
    __stcs(&out[v2], c);
    __stcs(&out[v3], d);
}

extern "C" void kernel_launch(void* const* d_in, const int* in_sizes, int n_in,
                              void* d_out, int out_size)
{
    const float4* x      = (const float4*)d_in[0];
    const float*  patch  = (const float*)d_in[1];
    const int2*   offs   = (const int2*)d_in[2];
    float4*       out    = (float4*)d_out;

    const int blocks = TOTAL_V4 / TILE;  // 9408, exact
    random_prompter_kernel<<<blocks, TPB>>>(x, patch, offs, out);
}

// round 4
// speedup vs baseline: 1.0052x; 1.0052x over previous
#include <cuda_runtime.h>
#include <cuda_bf16.h>

// RandomPrompter: out[b,c,h,w] = x[b,c,h,w] + (patch inside per-sample 30x30 window)
// Shapes: x [256,3,224,224] f32, patch [1,3,30,30] f32, offsets [256,2] i32.
//
// Pure streaming (308 MB, zero reuse). MLP=2 per thread (proven best), 512
// threads/block, L2-only loads (ldcg — skip L1 allocation), evict-first stores.

#define BATCH 256
#define CH    3
#define HH    224
#define WW    224
#define PSZ   30

#define W4        (WW / 4)                        // 56 float4 per row
#define TOTAL_V4  (BATCH * CH * HH * W4)          // 9,633,792 float4s
#define VPT       2                               // float4s per thread
#define TPB       512
#define TILE      (TPB * VPT)                     // 1024 float4s per block

__device__ __forceinline__ void patch_add(float4& val, int v,
                                          const float* __restrict__ patch,
                                          const int2* __restrict__ offsets)
{
    // v = ((b*3 + c)*224 + h)*56 + w4
    int w4 = v % W4;
    int t  = v / W4;
    int h  = t % HH;
    int t2 = t / HH;
    int c  = t2 % CH;
    int b  = t2 / CH;

    int2 off = __ldg(&offsets[b]);   // (row, col), each in [0, 194)
    int dh = h - off.x;
    if ((unsigned)dh < (unsigned)PSZ) {
        const float* prow = patch + (c * PSZ + dh) * PSZ;
        int dw = w4 * 4 - off.y;
        if ((unsigned)(dw + 0) < (unsigned)PSZ) val.x += __ldg(&prow[dw + 0]);
        if ((unsigned)(dw + 1) < (unsigned)PSZ) val.y += __ldg(&prow[dw + 1]);
        if ((unsigned)(dw + 2) < (unsigned)PSZ) val.z += __ldg(&prow[dw + 2]);
        if ((unsigned)(dw + 3) < (unsigned)PSZ) val.w += __ldg(&prow[dw + 3]);
    }
}

__global__ __launch_bounds__(TPB) void random_prompter_kernel(
    const float4* __restrict__ x,
    const float* __restrict__ patch,
    const int2* __restrict__ offsets,
    float4* __restrict__ out)
{
    int base = blockIdx.x * TILE + threadIdx.x;
    int v0 = base;
    int v1 = base + TPB;

    // TOTAL_V4 (9,633,792) is divisible by TILE (1024): 9408 blocks, no tail.
    // Both loads issued before either consumes (MLP=2), L2-only caching.
    float4 a = __ldcg(&x[v0]);
    float4 b = __ldcg(&x[v1]);

    patch_add(a, v0, patch, offsets);
    patch_add(b, v1, patch, offsets);

    __stcs(&out[v0], a);
    __stcs(&out[v1], b);
}

extern "C" void kernel_launch(void* const* d_in, const int* in_sizes, int n_in,
                              void* d_out, int out_size)
{
    const float4* x      = (const float4*)d_in[0];
    const float*  patch  = (const float*)d_in[1];
    const int2*   offs   = (const int2*)d_in[2];
    float4*       out    = (float4*)d_out;

    const int blocks = TOTAL_V4 / TILE;  // 9408, exact
    random_prompter_kernel<<<blocks, TPB>>>(x, patch, offs, out);
}